// round 8
// baseline (speedup 1.0000x reference)
#include <cuda_runtime.h>
#include <cuda_fp16.h>
#include <cstdint>

#define N_OUT   11008
#define K_IN    4096
#define M_TOK   32
#define NTILES  1376      // 8-channel output tiles
#define CNT     5         // tiles per CTA
#define GRID    276       // ceil(1376/5): single wave at occ 2 on 148+ SMs

// Pre-converted x image, staging order: [(w*4+r)*512 + row*16 + b*8 + u] 16B units
__device__ uint4 g_xh[16384];   // 256 KB

__device__ __forceinline__ void mma16816(float c[4],
                                         unsigned a0, unsigned a1, unsigned a2, unsigned a3,
                                         unsigned b0, unsigned b1) {
    asm volatile(
        "mma.sync.aligned.m16n8k16.row.col.f32.f16.f16.f32 "
        "{%0,%1,%2,%3}, {%4,%5,%6,%7}, {%8,%9}, {%0,%1,%2,%3};\n"
        : "+f"(c[0]), "+f"(c[1]), "+f"(c[2]), "+f"(c[3])
        : "r"(a0), "r"(a1), "r"(a2), "r"(a3), "r"(b0), "r"(b1));
}

// Pack byte0 of four int32s (low byte == int8 bits)
__device__ __forceinline__ unsigned pack4(int4 v) {
    unsigned t0 = __byte_perm((unsigned)v.x, (unsigned)v.y, 0x0040);
    unsigned t1 = __byte_perm((unsigned)v.z, (unsigned)v.w, 0x0040);
    return __byte_perm(t0, t1, 0x5410);
}

__device__ __forceinline__ void loadW(int4 W[4], const int* p) {
#pragma unroll
    for (int s = 0; s < 4; s++) W[s] = *reinterpret_cast<const int4*>(p + s * 4);
}

// ---- Pre-kernel: x fp32 -> fp16, staging-ordered image ----
// unit t: w=t>>11, r=(t>>9)&3, lin=t&511; row=lin>>4, bu=lin&15
// holds halves for token=row, k = w*512 + r*128 + bu*8 + {0..7}
__global__ void x_prep(const float* __restrict__ x) {
    int t = blockIdx.x * 256 + threadIdx.x;            // 0..16383
    int w = t >> 11, r = (t >> 9) & 3, lin = t & 511;
    int row = lin >> 4, bu = lin & 15;
    int k = w * 512 + r * 128 + bu * 8;
    const float* src = x + (size_t)row * K_IN + k;
    float4 f0 = *reinterpret_cast<const float4*>(src);
    float4 f1 = *reinterpret_cast<const float4*>(src + 4);
    __half2 h0 = __floats2half2_rn(f0.x, f0.y);
    __half2 h1 = __floats2half2_rn(f0.z, f0.w);
    __half2 h2 = __floats2half2_rn(f1.x, f1.y);
    __half2 h3 = __floats2half2_rn(f1.z, f1.w);
    uint4 v;
    v.x = *reinterpret_cast<unsigned*>(&h0);
    v.y = *reinterpret_cast<unsigned*>(&h1);
    v.z = *reinterpret_cast<unsigned*>(&h2);
    v.w = *reinterpret_cast<unsigned*>(&h3);
    g_xh[t] = v;
}

// ---- Main fused kernel: one wave, warps split K, fused reduce+epilogue ----
// k-permutation (audited, unchanged): thread (g=lane/4, tg=lane%4) owns logical
// k = tg*16 + {0..15} per k64 chunk; mma step s uses logical k tg*16+4s+{0,1} at
// hw slots {2tg,2tg+1} and +{2,3} at {2tg+8,2tg+9}; A from smem uses same map.
__global__ void __launch_bounds__(256, 2)
qlinear_fused(const int* __restrict__ qw, const float* __restrict__ scales,
              const float* __restrict__ bias, float* __restrict__ out) {
    extern __shared__ __align__(16) unsigned char smem[];
    const int t = threadIdx.x, w = t >> 5, lane = t & 31;
    const int g = lane >> 2, tg = lane & 3;
    const int tile0 = blockIdx.x * CNT;

    // Per-nt weight base pointers (clamped for masked tiles)
    const int* wb[CNT];
#pragma unroll
    for (int nt = 0; nt < CNT; nt++) {
        int tile = tile0 + nt; if (tile > NTILES - 1) tile = NTILES - 1;
        wb[nt] = qw + (size_t)(tile * 8 + g) * K_IN + w * 512 + tg * 16;
    }

    float c[CNT][2][4];
#pragma unroll
    for (int nt = 0; nt < CNT; nt++)
#pragma unroll
        for (int mh = 0; mh < 2; mh++)
#pragma unroll
            for (int q = 0; q < 4; q++) c[nt][mh][q] = 0.f;

    const __half2 magic = __halves2half2(__ushort_as_half(0x6480), __ushort_as_half(0x6480));

    int4 W[2][4];
    loadW(W[0], wb[0]);                       // (r=0, kc=0, nt=0)

#pragma unroll 1
    for (int r = 0; r < 4; r++) {
        __syncwarp();
        // Stage this warp's 8KB x region for round r (32 tok x 128 k, fp16)
        const uint4* src = g_xh + (w * 4 + r) * 512;
        unsigned char* dst = smem + w * 8192;
#pragma unroll
        for (int i = 0; i < 16; i++) {
            int lin = i * 32 + lane;
            int row = lin >> 4, b = (lin >> 3) & 1, u = lin & 7;
            uint4 v = src[lin];
            *reinterpret_cast<uint4*>(dst + row * 256 + b * 128 + ((u ^ (row & 7)) << 4)) = v;
        }
        __syncwarp();

#pragma unroll
        for (int kc = 0; kc < 2; kc++) {
            // A fragments: rows g+8rr, 16 halves each, swizzled
            unsigned A[4][8];
#pragma unroll
            for (int rr = 0; rr < 4; rr++) {
                const unsigned char* base = dst + (g + 8 * rr) * 256 + kc * 128;
                uint4 lo = *reinterpret_cast<const uint4*>(base + (((tg * 2 + 0) ^ g) << 4));
                uint4 hi = *reinterpret_cast<const uint4*>(base + (((tg * 2 + 1) ^ g) << 4));
                A[rr][0] = lo.x; A[rr][1] = lo.y; A[rr][2] = lo.z; A[rr][3] = lo.w;
                A[rr][4] = hi.x; A[rr][5] = hi.y; A[rr][6] = hi.z; A[rr][7] = hi.w;
            }
#pragma unroll
            for (int nt = 0; nt < CNT; nt++) {
                const int j = kc * CNT + nt;
                const int pc = j & 1;
                // one-ahead weight prefetch (flattened kc,nt; crosses round boundary)
                if (nt < CNT - 1)      loadW(W[pc ^ 1], wb[nt + 1] + r * 128 + kc * 64);
                else if (kc == 0)      loadW(W[pc ^ 1], wb[0] + r * 128 + 64);
                else if (r < 3)        loadW(W[pc ^ 1], wb[0] + (r + 1) * 128);

#pragma unroll
                for (int s = 0; s < 4; s++) {
                    unsigned packed = pack4(W[pc][s]);
                    unsigned ts = packed ^ 0x80808080u;
                    unsigned lo = __byte_perm(ts, 0x64646464u, 0x4140);
                    unsigned hi = __byte_perm(ts, 0x64646464u, 0x4342);
                    __half2 b0h = __hsub2(*reinterpret_cast<__half2*>(&lo), magic);
                    __half2 b1h = __hsub2(*reinterpret_cast<__half2*>(&hi), magic);
                    unsigned b0 = *reinterpret_cast<unsigned*>(&b0h);
                    unsigned b1 = *reinterpret_cast<unsigned*>(&b1h);
                    mma16816(c[nt][0], A[0][2*s], A[1][2*s], A[0][2*s+1], A[1][2*s+1], b0, b1);
                    mma16816(c[nt][1], A[2][2*s], A[3][2*s], A[2][2*s+1], A[3][2*s+1], b0, b1);
                }
            }
        }
    }

    // ---- Intra-CTA reduction over the 8 k-slice warps + fused epilogue ----
    __syncthreads();
    float* red = reinterpret_cast<float*>(smem);   // [nt][tok][ch][w'] = 40KB
#pragma unroll
    for (int nt = 0; nt < CNT; nt++)
#pragma unroll
        for (int mh = 0; mh < 2; mh++)
#pragma unroll
            for (int q = 0; q < 4; q++) {
                int tok = mh * 16 + g + ((q >> 1) << 3);
                int ch  = tg * 2 + (q & 1);
                red[(nt * 256 + tok * 8 + ch) * 8 + ((w + tok) & 7)] = c[nt][mh][q];
            }
    __syncthreads();

#pragma unroll
    for (int i = 0; i < CNT; i++) {
        int e = t + i * 256;                        // 0..1279
        int nt = e >> 8, rem = e & 255, tok = rem >> 3, ch = rem & 7;
        int tile = tile0 + nt;
        if (tile < NTILES) {
            const float* p = red + e * 8;
            float4 a = *reinterpret_cast<const float4*>(p);
            float4 b = *reinterpret_cast<const float4*>(p + 4);
            float s = ((a.x + a.y) + (a.z + a.w)) + ((b.x + b.y) + (b.z + b.w));
            int n = tile * 8 + ch;
            out[(size_t)tok * N_OUT + n] = s * scales[n] + bias[n];
        }
    }
}

extern "C" void kernel_launch(void* const* d_in, const int* in_sizes, int n_in,
                              void* d_out, int out_size) {
    const float* x      = (const float*)d_in[0];
    const int*   qw     = (const int*)d_in[1];
    const float* scales = (const float*)d_in[2];
    const float* bias   = (const float*)d_in[3];
    float*       out    = (float*)d_out;

    cudaFuncSetAttribute((const void*)qlinear_fused,
                         cudaFuncAttributeMaxDynamicSharedMemorySize, 65536);
    x_prep<<<64, 256>>>(x);
    qlinear_fused<<<GRID, 256, 65536>>>(qw, scales, bias, out);
}

// round 9
// speedup vs baseline: 1.4012x; 1.4012x over previous
#include <cuda_runtime.h>
#include <cuda_fp16.h>
#include <cstdint>

#define N_OUT   11008
#define K_IN    4096
#define M_TOK   32
#define NTILES  1376      // 8-channel output tiles
#define CNT     5         // tiles per CTA
#define GRID    276       // ceil(1376/5): single wave at occ 2

// Pre-converted x image, staging order: [(w*4+r)*512 + row*16 + b*8 + u] 16B units
__device__ uint4 g_xh[16384];   // 256 KB

__device__ __forceinline__ void mma16816(float c[4],
                                         unsigned a0, unsigned a1, unsigned a2, unsigned a3,
                                         unsigned b0, unsigned b1) {
    asm volatile(
        "mma.sync.aligned.m16n8k16.row.col.f32.f16.f16.f32 "
        "{%0,%1,%2,%3}, {%4,%5,%6,%7}, {%8,%9}, {%0,%1,%2,%3};\n"
        : "+f"(c[0]), "+f"(c[1]), "+f"(c[2]), "+f"(c[3])
        : "r"(a0), "r"(a1), "r"(a2), "r"(a3), "r"(b0), "r"(b1));
}

// Pack byte0 of four int32s (low byte == int8 bits)
__device__ __forceinline__ unsigned pack4(int4 v) {
    unsigned t0 = __byte_perm((unsigned)v.x, (unsigned)v.y, 0x0040);
    unsigned t1 = __byte_perm((unsigned)v.z, (unsigned)v.w, 0x0040);
    return __byte_perm(t0, t1, 0x5410);
}

__device__ __forceinline__ void loadW(int4 W[4], const int* __restrict__ p) {
#pragma unroll
    for (int s = 0; s < 4; s++) W[s] = *reinterpret_cast<const int4*>(p + s * 4);
}

// ---- Pre-kernel: x fp32 -> fp16, staging-ordered image ----
__global__ void x_prep(const float* __restrict__ x) {
    int t = blockIdx.x * 256 + threadIdx.x;            // 0..16383
    int w = t >> 11, r = (t >> 9) & 3, lin = t & 511;
    int row = lin >> 4, bu = lin & 15;
    int k = w * 512 + r * 128 + bu * 8;
    const float* src = x + (size_t)row * K_IN + k;
    float4 f0 = *reinterpret_cast<const float4*>(src);
    float4 f1 = *reinterpret_cast<const float4*>(src + 4);
    __half2 h0 = __floats2half2_rn(f0.x, f0.y);
    __half2 h1 = __floats2half2_rn(f0.z, f0.w);
    __half2 h2 = __floats2half2_rn(f1.x, f1.y);
    __half2 h3 = __floats2half2_rn(f1.z, f1.w);
    uint4 v;
    v.x = *reinterpret_cast<unsigned*>(&h0);
    v.y = *reinterpret_cast<unsigned*>(&h1);
    v.z = *reinterpret_cast<unsigned*>(&h2);
    v.w = *reinterpret_cast<unsigned*>(&h3);
    g_xh[t] = v;
}

// ---- Main fused kernel: single wave, warps split K 8-way, fused epilogue ----
// k-permutation (audited): thread (g=lane/4, tg=lane%4) owns logical
// k = tg*16 + {0..15} per k64 chunk; mma step s uses logical k tg*16+4s+{0,1} at
// hw slots {2tg,2tg+1} and +{2,3} at {2tg+8,2tg+9}; A from smem uses same map.
__global__ void __launch_bounds__(256, 2)
qlinear_fused(const int* __restrict__ qw, const float* __restrict__ scales,
              const float* __restrict__ bias, float* __restrict__ out) {
    extern __shared__ __align__(16) unsigned char smem[];
    const int t = threadIdx.x, w = t >> 5, lane = t & 31;
    const int g = lane >> 2, tg = lane & 3;
    const int tile0 = blockIdx.x * CNT;

    // Lean addressing: one base pointer + small int element-offsets per nt.
    const int tb0 = (tile0 < NTILES) ? tile0 : (NTILES - 1);
    const int* wb0 = qw + (size_t)(tb0 * 8 + g) * K_IN + w * 512 + tg * 16;
    int off[CNT];
#pragma unroll
    for (int nt = 0; nt < CNT; nt++) {
        int tile = tile0 + nt; if (tile > NTILES - 1) tile = NTILES - 1;
        off[nt] = (tile - tb0) * (8 * K_IN);           // element offset, fits int32
    }

    float c[CNT][2][4];
#pragma unroll
    for (int nt = 0; nt < CNT; nt++)
#pragma unroll
        for (int mh = 0; mh < 2; mh++)
#pragma unroll
            for (int q = 0; q < 4; q++) c[nt][mh][q] = 0.f;

    const __half2 magic = __halves2half2(__ushort_as_half(0x6480), __ushort_as_half(0x6480));

    int4 Wraw[4];
    loadW(Wraw, wb0);                                   // (r=0, kc=0, nt=0)

#pragma unroll 1
    for (int r = 0; r < 4; r++) {
        __syncwarp();
        // Stage this warp's 8KB x region for round r (32 tok x 128 k, fp16)
        const uint4* src = g_xh + (w * 4 + r) * 512;
        unsigned char* dst = smem + w * 8192;
#pragma unroll
        for (int i = 0; i < 16; i++) {
            int lin = i * 32 + lane;
            int row = lin >> 4, b = (lin >> 3) & 1, u = lin & 7;
            uint4 v = src[lin];
            *reinterpret_cast<uint4*>(dst + row * 256 + b * 128 + ((u ^ (row & 7)) << 4)) = v;
        }
        __syncwarp();

#pragma unroll
        for (int kc = 0; kc < 2; kc++) {
            // A fragments: rows g+8rr, 16 halves each, swizzled
            unsigned A[4][8];
#pragma unroll
            for (int rr = 0; rr < 4; rr++) {
                const unsigned char* base = dst + (g + 8 * rr) * 256 + kc * 128;
                uint4 lo = *reinterpret_cast<const uint4*>(base + (((tg * 2 + 0) ^ g) << 4));
                uint4 hi = *reinterpret_cast<const uint4*>(base + (((tg * 2 + 1) ^ g) << 4));
                A[rr][0] = lo.x; A[rr][1] = lo.y; A[rr][2] = lo.z; A[rr][3] = lo.w;
                A[rr][4] = hi.x; A[rr][5] = hi.y; A[rr][6] = hi.z; A[rr][7] = hi.w;
            }
#pragma unroll
            for (int nt = 0; nt < CNT; nt++) {
                // Extract this iteration's weights, freeing Wraw for the prefetch.
                unsigned ps[4];
#pragma unroll
                for (int s = 0; s < 4; s++) ps[s] = pack4(Wraw[s]);

                // One-ahead prefetch of the next (r,kc,nt) into Wraw.
                {
                    const int nt2 = (nt < CNT - 1) ? nt + 1 : 0;
                    const int kc2 = (nt < CNT - 1) ? kc : (kc ^ 1);
                    const int rstep = (nt == CNT - 1 && kc == 1) ? 1 : 0;
                    if (!(r == 3 && kc == 1 && nt == CNT - 1)) {
                        const int r2 = r + rstep;
                        loadW(Wraw, wb0 + off[nt2] + r2 * 128 + kc2 * 64);
                    }
                }

#pragma unroll
                for (int s = 0; s < 4; s++) {
                    unsigned ts = ps[s] ^ 0x80808080u;
                    unsigned lo = __byte_perm(ts, 0x64646464u, 0x4140);
                    unsigned hi = __byte_perm(ts, 0x64646464u, 0x4342);
                    __half2 b0h = __hsub2(*reinterpret_cast<__half2*>(&lo), magic);
                    __half2 b1h = __hsub2(*reinterpret_cast<__half2*>(&hi), magic);
                    unsigned b0 = *reinterpret_cast<unsigned*>(&b0h);
                    unsigned b1 = *reinterpret_cast<unsigned*>(&b1h);
                    mma16816(c[nt][0], A[0][2*s], A[1][2*s], A[0][2*s+1], A[1][2*s+1], b0, b1);
                    mma16816(c[nt][1], A[2][2*s], A[3][2*s], A[2][2*s+1], A[3][2*s+1], b0, b1);
                }
            }
        }
    }

    // ---- Intra-CTA reduction over the 8 k-slice warps + fused epilogue ----
    __syncthreads();
    float* red = reinterpret_cast<float*>(smem);   // [nt][tok][ch][w'] = 40KB
#pragma unroll
    for (int nt = 0; nt < CNT; nt++)
#pragma unroll
        for (int mh = 0; mh < 2; mh++)
#pragma unroll
            for (int q = 0; q < 4; q++) {
                int tok = mh * 16 + g + ((q >> 1) << 3);
                int ch  = tg * 2 + (q & 1);
                red[(nt * 256 + tok * 8 + ch) * 8 + ((w + tok) & 7)] = c[nt][mh][q];
            }
    __syncthreads();

#pragma unroll
    for (int i = 0; i < CNT; i++) {
        int e = t + i * 256;                        // 0..1279
        int nt = e >> 8, rem = e & 255, tok = rem >> 3, ch = rem & 7;
        int tile = tile0 + nt;
        if (tile < NTILES) {
            const float* p = red + e * 8;
            float4 a = *reinterpret_cast<const float4*>(p);
            float4 b = *reinterpret_cast<const float4*>(p + 4);
            float s = ((a.x + a.y) + (a.z + a.w)) + ((b.x + b.y) + (b.z + b.w));
            int n = tile * 8 + ch;
            out[(size_t)tok * N_OUT + n] = s * scales[n] + bias[n];
        }
    }
}

extern "C" void kernel_launch(void* const* d_in, const int* in_sizes, int n_in,
                              void* d_out, int out_size) {
    const float* x      = (const float*)d_in[0];
    const int*   qw     = (const int*)d_in[1];
    const float* scales = (const float*)d_in[2];
    const float* bias   = (const float*)d_in[3];
    float*       out    = (float*)d_out;

    cudaFuncSetAttribute((const void*)qlinear_fused,
                         cudaFuncAttributeMaxDynamicSharedMemorySize, 65536);
    x_prep<<<64, 256>>>(x);
    qlinear_fused<<<GRID, 256, 65536>>>(qw, scales, bias, out);
}